// round 4
// baseline (speedup 1.0000x reference)
#include <cuda_runtime.h>
#include <math_constants.h>

#define NB 4096
#define NC 1000
#define ND 2048
#define CP 1024
#define TILE 64
#define NTILE (CP / TILE)                 // 16
#define NPAIRS (NTILE * (NTILE + 1) / 2)  // 136

// Scratch (device globals — no allocation allowed)
__device__ float g_dist[CP * CP];   // Dist[i*CP + j], only i,j < NC valid
__device__ float g_sq[CP];          // raw row norms sum(W[c,:]^2)
__device__ float g_ymax[NB];
__device__ int   g_j0[NB];

// ---------------------------------------------------------------------------
// Kernel 1: per-row argmax + max of prediction
// ---------------------------------------------------------------------------
__global__ void __launch_bounds__(128) argmax_kernel(const float* __restrict__ pred) {
    int b = blockIdx.x;
    const float* row = pred + (long)b * NC;
    float best = -CUDART_INF_F;
    int bidx = NC;
    for (int c = threadIdx.x; c < NC; c += 128) {
        float v = row[c];
        if (v > best) { best = v; bidx = c; }   // strided: lower c seen first per thread
    }
    for (int o = 16; o > 0; o >>= 1) {
        float v2 = __shfl_down_sync(0xFFFFFFFFu, best, o);
        int   i2 = __shfl_down_sync(0xFFFFFFFFu, bidx, o);
        if (v2 > best || (v2 == best && i2 < bidx)) { best = v2; bidx = i2; }
    }
    __shared__ float sv[4];
    __shared__ int   si[4];
    int w = threadIdx.x >> 5;
    if ((threadIdx.x & 31) == 0) { sv[w] = best; si[w] = bidx; }
    __syncthreads();
    if (threadIdx.x == 0) {
        for (int i = 1; i < 4; i++) {
            if (sv[i] > best || (sv[i] == best && si[i] < bidx)) { best = sv[i]; bidx = si[i]; }
        }
        g_ymax[b] = best;
        g_j0[b] = bidx;
    }
}

// ---------------------------------------------------------------------------
// Kernel 2: raw row norms of W (no k^2 scaling; applied in dist epilogue)
// ---------------------------------------------------------------------------
__global__ void __launch_bounds__(256) norms_kernel(const float* __restrict__ W) {
    int c = blockIdx.x;
    const float* row = W + (long)c * ND;
    float s = 0.f;
    for (int d = threadIdx.x * 4; d < ND; d += 256 * 4) {
        float4 v = *(const float4*)(row + d);
        s += v.x * v.x + v.y * v.y + v.z * v.z + v.w * v.w;
    }
    for (int o = 16; o > 0; o >>= 1) s += __shfl_down_sync(0xFFFFFFFFu, s, o);
    __shared__ float sm[8];
    int w = threadIdx.x >> 5;
    if ((threadIdx.x & 31) == 0) sm[w] = s;
    __syncthreads();
    if (threadIdx.x == 0) {
        float t = 0.f;
        for (int i = 0; i < 8; i++) t += sm[i];
        g_sq[c] = t;
    }
}

// ---------------------------------------------------------------------------
// Kernel 3: triangular Gram G = W W^T (64x64 tiles), fused distance epilogue
//   Dist[i,j] = k * sqrt(max(sq_i + sq_j - 2*G_ij, 0)), written symmetrically
// ---------------------------------------------------------------------------
__global__ void __launch_bounds__(256) gram_dist_kernel(const float* __restrict__ W,
                                                        const float* __restrict__ Kin) {
    // map linear block id -> upper-triangular tile pair (ti <= tj)
    int p = blockIdx.x;
    int ti = 0;
    while (p >= NTILE - ti) { p -= NTILE - ti; ti++; }
    int tj = ti + p;

    __shared__ float As[32][TILE];  // [k][row]  (transposed for conflict-free reads)
    __shared__ float Bs[32][TILE];

    int tid = threadIdx.x;
    int tx = tid & 15, ty = tid >> 4;
    int rowA = ti * TILE, rowB = tj * TILE;

    float acc[4][4] = {};

    for (int k0 = 0; k0 < ND; k0 += 32) {
        #pragma unroll
        for (int l = tid; l < 512; l += 256) {
            int r = l >> 3, q = l & 7;
            int gr = rowA + r;
            float4 v = make_float4(0.f, 0.f, 0.f, 0.f);
            if (gr < NC) v = *(const float4*)(W + (long)gr * ND + k0 + q * 4);
            As[q * 4 + 0][r] = v.x; As[q * 4 + 1][r] = v.y;
            As[q * 4 + 2][r] = v.z; As[q * 4 + 3][r] = v.w;
        }
        #pragma unroll
        for (int l = tid; l < 512; l += 256) {
            int r = l >> 3, q = l & 7;
            int gr = rowB + r;
            float4 v = make_float4(0.f, 0.f, 0.f, 0.f);
            if (gr < NC) v = *(const float4*)(W + (long)gr * ND + k0 + q * 4);
            Bs[q * 4 + 0][r] = v.x; Bs[q * 4 + 1][r] = v.y;
            Bs[q * 4 + 2][r] = v.z; Bs[q * 4 + 3][r] = v.w;
        }
        __syncthreads();
        #pragma unroll
        for (int kk = 0; kk < 32; kk++) {
            float4 a = *(const float4*)&As[kk][ty * 4];
            float4 b = *(const float4*)&Bs[kk][tx * 4];
            acc[0][0] += a.x * b.x; acc[0][1] += a.x * b.y; acc[0][2] += a.x * b.z; acc[0][3] += a.x * b.w;
            acc[1][0] += a.y * b.x; acc[1][1] += a.y * b.y; acc[1][2] += a.y * b.z; acc[1][3] += a.y * b.w;
            acc[2][0] += a.z * b.x; acc[2][1] += a.z * b.y; acc[2][2] += a.z * b.z; acc[2][3] += a.z * b.w;
            acc[3][0] += a.w * b.x; acc[3][1] += a.w * b.y; acc[3][2] += a.w * b.z; acc[3][3] += a.w * b.w;
        }
        __syncthreads();
    }

    // epilogue: distances, written to both (i,j) and (j,i)
    const float DS = (float)(1.0 / (double)0.224f);   // matches float32(0.224) min-std path
    float kscale = Kin[0] * DS;

    float sqa[4], sqb[4];
    #pragma unroll
    for (int i = 0; i < 4; i++) {
        int gi = rowA + ty * 4 + i;
        sqa[i] = (gi < NC) ? g_sq[gi] : 0.f;
        int gj = rowB + tx * 4 + i;
        sqb[i] = (gj < NC) ? g_sq[gj] : 0.f;
    }
    #pragma unroll
    for (int i = 0; i < 4; i++) {
        int gi = rowA + ty * 4 + i;
        if (gi >= NC) continue;
        #pragma unroll
        for (int j = 0; j < 4; j++) {
            int gj = rowB + tx * 4 + j;
            if (gj >= NC) continue;
            float d2 = sqa[i] + sqb[j] - 2.f * acc[i][j];
            float d = kscale * sqrtf(fmaxf(d2, 0.f));
            g_dist[gi * CP + gj] = d;
            g_dist[gj * CP + gi] = d;
        }
    }
}

// ---------------------------------------------------------------------------
// Kernel 4: out[b] = min_{c != j0} (ymax[b] - pred[b,c]) / Dist[j0[b], c]
// ---------------------------------------------------------------------------
__global__ void __launch_bounds__(128) final_kernel(const float* __restrict__ pred,
                                                    float* __restrict__ out) {
    int b = blockIdx.x;
    int j0 = g_j0[b];
    float ym = g_ymax[b];
    const float* dr = g_dist + (long)j0 * CP;
    const float* pr = pred + (long)b * NC;
    float mn = CUDART_INF_F;
    for (int c = threadIdx.x; c < NC; c += 128) {
        if (c == j0) continue;
        float r = (ym - pr[c]) / dr[c];
        mn = fminf(mn, r);
    }
    for (int o = 16; o > 0; o >>= 1)
        mn = fminf(mn, __shfl_down_sync(0xFFFFFFFFu, mn, o));
    __shared__ float sm[4];
    int w = threadIdx.x >> 5;
    if ((threadIdx.x & 31) == 0) sm[w] = mn;
    __syncthreads();
    if (threadIdx.x == 0) {
        out[b] = fminf(fminf(sm[0], sm[1]), fminf(sm[2], sm[3]));
    }
}

// ---------------------------------------------------------------------------
extern "C" void kernel_launch(void* const* d_in, const int* in_sizes, int n_in,
                              void* d_out, int out_size) {
    const float* pred = (const float*)d_in[0];
    const float* W    = (const float*)d_in[1];
    const float* K    = (const float*)d_in[2];
    float* out = (float*)d_out;

    argmax_kernel<<<NB, 128>>>(pred);
    norms_kernel<<<NC, 256>>>(W);
    gram_dist_kernel<<<NPAIRS, 256>>>(W, K);
    final_kernel<<<NB, 128>>>(pred, out);
}

// round 5
// speedup vs baseline: 1.0023x; 1.0023x over previous
#include <cuda_runtime.h>
#include <math_constants.h>

#define NB 4096
#define NC 1000
#define ND 2048
#define CP 1024
#define TILE 64
#define NTILE (CP / TILE)                 // 16
#define NPAIRS (NTILE * (NTILE + 1) / 2)  // 136

// Scratch (device globals — no allocation allowed)
__device__ float g_dist[CP * CP];   // Dist[i*CP + j], only i,j < NC valid
__device__ float g_sq[CP];          // raw row norms sum(W[c,:]^2)
__device__ float g_ymax[NB];
__device__ int   g_j0[NB];

// ---------------------------------------------------------------------------
// Kernel 1: per-row argmax + max of prediction
// ---------------------------------------------------------------------------
__global__ void __launch_bounds__(128) argmax_kernel(const float* __restrict__ pred) {
    int b = blockIdx.x;
    const float* row = pred + (long)b * NC;
    float best = -CUDART_INF_F;
    int bidx = NC;
    for (int c = threadIdx.x; c < NC; c += 128) {
        float v = row[c];
        if (v > best) { best = v; bidx = c; }   // strided: lower c seen first per thread
    }
    for (int o = 16; o > 0; o >>= 1) {
        float v2 = __shfl_down_sync(0xFFFFFFFFu, best, o);
        int   i2 = __shfl_down_sync(0xFFFFFFFFu, bidx, o);
        if (v2 > best || (v2 == best && i2 < bidx)) { best = v2; bidx = i2; }
    }
    __shared__ float sv[4];
    __shared__ int   si[4];
    int w = threadIdx.x >> 5;
    if ((threadIdx.x & 31) == 0) { sv[w] = best; si[w] = bidx; }
    __syncthreads();
    if (threadIdx.x == 0) {
        for (int i = 1; i < 4; i++) {
            if (sv[i] > best || (sv[i] == best && si[i] < bidx)) { best = sv[i]; bidx = si[i]; }
        }
        g_ymax[b] = best;
        g_j0[b] = bidx;
    }
}

// ---------------------------------------------------------------------------
// Kernel 2: raw row norms of W (no k^2 scaling; applied in dist epilogue)
// ---------------------------------------------------------------------------
__global__ void __launch_bounds__(256) norms_kernel(const float* __restrict__ W) {
    int c = blockIdx.x;
    const float* row = W + (long)c * ND;
    float s = 0.f;
    for (int d = threadIdx.x * 4; d < ND; d += 256 * 4) {
        float4 v = *(const float4*)(row + d);
        s += v.x * v.x + v.y * v.y + v.z * v.z + v.w * v.w;
    }
    for (int o = 16; o > 0; o >>= 1) s += __shfl_down_sync(0xFFFFFFFFu, s, o);
    __shared__ float sm[8];
    int w = threadIdx.x >> 5;
    if ((threadIdx.x & 31) == 0) sm[w] = s;
    __syncthreads();
    if (threadIdx.x == 0) {
        float t = 0.f;
        for (int i = 0; i < 8; i++) t += sm[i];
        g_sq[c] = t;
    }
}

// ---------------------------------------------------------------------------
// Kernel 3: triangular Gram G = W W^T (64x64 tiles), fused distance epilogue
//   Dist[i,j] = k * sqrt(max(sq_i + sq_j - 2*G_ij, 0)), written symmetrically
// ---------------------------------------------------------------------------
__global__ void __launch_bounds__(256) gram_dist_kernel(const float* __restrict__ W,
                                                        const float* __restrict__ Kin) {
    // map linear block id -> upper-triangular tile pair (ti <= tj)
    int p = blockIdx.x;
    int ti = 0;
    while (p >= NTILE - ti) { p -= NTILE - ti; ti++; }
    int tj = ti + p;

    __shared__ float As[32][TILE];  // [k][row]  (transposed for conflict-free reads)
    __shared__ float Bs[32][TILE];

    int tid = threadIdx.x;
    int tx = tid & 15, ty = tid >> 4;
    int rowA = ti * TILE, rowB = tj * TILE;

    float acc[4][4] = {};

    for (int k0 = 0; k0 < ND; k0 += 32) {
        #pragma unroll
        for (int l = tid; l < 512; l += 256) {
            int r = l >> 3, q = l & 7;
            int gr = rowA + r;
            float4 v = make_float4(0.f, 0.f, 0.f, 0.f);
            if (gr < NC) v = *(const float4*)(W + (long)gr * ND + k0 + q * 4);
            As[q * 4 + 0][r] = v.x; As[q * 4 + 1][r] = v.y;
            As[q * 4 + 2][r] = v.z; As[q * 4 + 3][r] = v.w;
        }
        #pragma unroll
        for (int l = tid; l < 512; l += 256) {
            int r = l >> 3, q = l & 7;
            int gr = rowB + r;
            float4 v = make_float4(0.f, 0.f, 0.f, 0.f);
            if (gr < NC) v = *(const float4*)(W + (long)gr * ND + k0 + q * 4);
            Bs[q * 4 + 0][r] = v.x; Bs[q * 4 + 1][r] = v.y;
            Bs[q * 4 + 2][r] = v.z; Bs[q * 4 + 3][r] = v.w;
        }
        __syncthreads();
        #pragma unroll
        for (int kk = 0; kk < 32; kk++) {
            float4 a = *(const float4*)&As[kk][ty * 4];
            float4 b = *(const float4*)&Bs[kk][tx * 4];
            acc[0][0] += a.x * b.x; acc[0][1] += a.x * b.y; acc[0][2] += a.x * b.z; acc[0][3] += a.x * b.w;
            acc[1][0] += a.y * b.x; acc[1][1] += a.y * b.y; acc[1][2] += a.y * b.z; acc[1][3] += a.y * b.w;
            acc[2][0] += a.z * b.x; acc[2][1] += a.z * b.y; acc[2][2] += a.z * b.z; acc[2][3] += a.z * b.w;
            acc[3][0] += a.w * b.x; acc[3][1] += a.w * b.y; acc[3][2] += a.w * b.z; acc[3][3] += a.w * b.w;
        }
        __syncthreads();
    }

    // epilogue: distances, written to both (i,j) and (j,i)
    const float DS = (float)(1.0 / (double)0.224f);   // matches float32(0.224) min-std path
    float kscale = Kin[0] * DS;

    float sqa[4], sqb[4];
    #pragma unroll
    for (int i = 0; i < 4; i++) {
        int gi = rowA + ty * 4 + i;
        sqa[i] = (gi < NC) ? g_sq[gi] : 0.f;
        int gj = rowB + tx * 4 + i;
        sqb[i] = (gj < NC) ? g_sq[gj] : 0.f;
    }
    #pragma unroll
    for (int i = 0; i < 4; i++) {
        int gi = rowA + ty * 4 + i;
        if (gi >= NC) continue;
        #pragma unroll
        for (int j = 0; j < 4; j++) {
            int gj = rowB + tx * 4 + j;
            if (gj >= NC) continue;
            float d2 = sqa[i] + sqb[j] - 2.f * acc[i][j];
            float d = kscale * sqrtf(fmaxf(d2, 0.f));
            g_dist[gi * CP + gj] = d;
            g_dist[gj * CP + gi] = d;
        }
    }
}

// ---------------------------------------------------------------------------
// Kernel 4: out[b] = min_{c != j0} (ymax[b] - pred[b,c]) / Dist[j0[b], c]
// ---------------------------------------------------------------------------
__global__ void __launch_bounds__(128) final_kernel(const float* __restrict__ pred,
                                                    float* __restrict__ out) {
    int b = blockIdx.x;
    int j0 = g_j0[b];
    float ym = g_ymax[b];
    const float* dr = g_dist + (long)j0 * CP;
    const float* pr = pred + (long)b * NC;
    float mn = CUDART_INF_F;
    for (int c = threadIdx.x; c < NC; c += 128) {
        if (c == j0) continue;
        float r = (ym - pr[c]) / dr[c];
        mn = fminf(mn, r);
    }
    for (int o = 16; o > 0; o >>= 1)
        mn = fminf(mn, __shfl_down_sync(0xFFFFFFFFu, mn, o));
    __shared__ float sm[4];
    int w = threadIdx.x >> 5;
    if ((threadIdx.x & 31) == 0) sm[w] = mn;
    __syncthreads();
    if (threadIdx.x == 0) {
        out[b] = fminf(fminf(sm[0], sm[1]), fminf(sm[2], sm[3]));
    }
}

// ---------------------------------------------------------------------------
extern "C" void kernel_launch(void* const* d_in, const int* in_sizes, int n_in,
                              void* d_out, int out_size) {
    const float* pred = (const float*)d_in[0];
    const float* W    = (const float*)d_in[1];
    const float* K    = (const float*)d_in[2];
    float* out = (float*)d_out;

    argmax_kernel<<<NB, 128>>>(pred);
    norms_kernel<<<NC, 256>>>(W);
    gram_dist_kernel<<<NPAIRS, 256>>>(W, K);
    final_kernel<<<NB, 128>>>(pred, out);
}